// round 1
// baseline (speedup 1.0000x reference)
#include <cuda_runtime.h>

// Problem constants
#define NPIXC   16384      // 128*128
#define NFC     8
#define NDC     8
#define NINC    16         // NF+ND
#define KC      9
#define MDC     16
#define NDMC    8
#define D0C     24         // MD+NDM
#define MLPHC   64
#define BC      16

#define PXB     8          // pixels per block (1 per warp)
#define THREADS 256

// shared-memory float offsets
#define WSTRIDE 2880       // per-pixel Wt: 9*16*20 (m padded 16->20)
#define GSTRIDE 2372       // per-pixel G: 16*148 (+4 pad for bank spread)
#define MSTRIDE 384        // per-pixel mlp_in: 16*24
#define OFF_W   0                       // 8*2880 = 23040
#define OFF_G   23040                   // 8*2372 = 18976
#define OFF_M   42016                   // 8*384  = 3072
#define OFF_W1  45088                   // 64*24  = 1536
#define OFF_B1  46624                   // 64
#define OFF_W2T 46688                   // 64*8   = 512 (transposed w2)
#define OFF_B2  47200                   // 8
#define OFF_O   47208                   // 8px * 128 = 1024
#define OFF_N   48232                   // 72 ints
#define SMEM_FLOATS 48304
#define SMEM_BYTES (SMEM_FLOATS * 4)

__global__ void __launch_bounds__(THREADS, 1)
lr_kernel(const float* __restrict__ y,     // [B][NF][NPIX]
          const float* __restrict__ nz,    // [B][ND][NPIX]
          const float* __restrict__ nz2,   // [B][NPIX][NDM]
          const float* __restrict__ wmap,  // [NPIX][K][MD][NIN]
          const float* __restrict__ w1,    // [64][24]
          const float* __restrict__ b1,    // [64]
          const float* __restrict__ w2,    // [8][64]
          const float* __restrict__ b2,    // [8]
          const int*   __restrict__ nidx,  // [NPIX][9]
          float*       __restrict__ out)   // [B][NF][NPIX]
{
    extern __shared__ float s[];
    float* sW  = s + OFF_W;
    float* sG  = s + OFF_G;
    float* sM  = s + OFF_M;
    float* sW1 = s + OFF_W1;
    float* sB1 = s + OFF_B1;
    float* sW2 = s + OFF_W2T;
    float* sB2 = s + OFF_B2;
    float* sO  = s + OFF_O;
    int*   sN  = (int*)(s + OFF_N);

    const int tid = threadIdx.x;
    const int p0  = blockIdx.x * PXB;

    // ---- small shared weights + neighbor indices ----
    for (int i = tid; i < 1536; i += THREADS) sW1[i] = w1[i];
    if (tid < 64) sB1[tid] = b1[tid];
    for (int i = tid; i < 512; i += THREADS)          // w2 transposed: sW2[i][f]
        sW2[i] = w2[(i & 7) * 64 + (i >> 3)];
    if (tid < 8) sB2[tid] = b2[tid];
    if (tid < 72) sN[tid] = nidx[p0 * 9 + tid];
    __syncthreads();

    // ---- gather features into sG[px][b][k][n] (b-stride 148) ----
    {
        const int px = tid & 7;
        const int fo = tid >> 3;   // 0..3
        #pragma unroll 1
        for (int it = 0; it < 72; ++it) {
            int f = it * 32 + fo;           // 0..2303 over (b,k,n)
            int n = f & 15;
            int k = (f >> 4) % 9;
            int b = f / 144;
            int q = sN[px * 9 + k];
            const float* src = (n < 8) ? y : nz;
            float v = src[(b * 8 + (n & 7)) * NPIXC + q];
            sG[px * GSTRIDE + b * 148 + k * 16 + n] = v;
        }
    }

    // ---- load + transpose weight_map into sW[px][k][n][20] ----
    {
        #pragma unroll 1
        for (int it = 0; it < 18; ++it) {
            int q  = it * THREADS + tid;    // float4 index over [px][k][m][n4]
            int n4 = q & 3;
            int m  = (q >> 2) & 15;
            int k  = (q >> 6) % 9;
            int px = q / 576;
            float4 v = ((const float4*)wmap)[(p0 + px) * 576 + k * 64 + m * 4 + n4];
            float* wb = sW + px * WSTRIDE + k * 320 + m;
            int nb = n4 * 4;
            wb[(nb + 0) * 20] = v.x;
            wb[(nb + 1) * 20] = v.y;
            wb[(nb + 2) * 20] = v.z;
            wb[(nb + 3) * 20] = v.w;
        }
    }
    __syncthreads();

    // ---- per-warp: one pixel ----
    const int lane = tid & 31;
    const int px   = tid >> 5;
    const int p    = p0 + px;
    const float* Gp = sG + px * GSTRIDE;
    const float* Wp = sW + px * WSTRIDE;
    float* Mp = sM + px * MSTRIDE;

    // einsum: thread tile 2 batches x 4 m
    {
        const int bp = lane >> 2;    // 0..7
        const int mq = lane & 3;     // 0..3
        const int b0 = bp * 2;
        const int m0 = mq * 4;

        float acc[8];
        #pragma unroll
        for (int i = 0; i < 8; ++i) acc[i] = 0.f;

        #pragma unroll 1
        for (int k = 0; k < 9; ++k) {
            const float* gb0 = Gp + b0 * 148 + k * 16;
            const float* gb1 = gb0 + 148;
            const float* wk  = Wp + k * 320 + m0;
            #pragma unroll
            for (int n4 = 0; n4 < 4; ++n4) {
                float4 g0 = *(const float4*)(gb0 + n4 * 4);
                float4 g1 = *(const float4*)(gb1 + n4 * 4);
                float g0a[4] = {g0.x, g0.y, g0.z, g0.w};
                float g1a[4] = {g1.x, g1.y, g1.z, g1.w};
                #pragma unroll
                for (int j = 0; j < 4; ++j) {
                    float4 w = *(const float4*)(wk + (n4 * 4 + j) * 20);
                    acc[0] = fmaf(g0a[j], w.x, acc[0]);
                    acc[1] = fmaf(g0a[j], w.y, acc[1]);
                    acc[2] = fmaf(g0a[j], w.z, acc[2]);
                    acc[3] = fmaf(g0a[j], w.w, acc[3]);
                    acc[4] = fmaf(g1a[j], w.x, acc[4]);
                    acc[5] = fmaf(g1a[j], w.y, acc[5]);
                    acc[6] = fmaf(g1a[j], w.z, acc[6]);
                    acc[7] = fmaf(g1a[j], w.w, acc[7]);
                }
            }
        }
        *(float4*)(Mp + b0 * 24 + m0)       = make_float4(acc[0], acc[1], acc[2], acc[3]);
        *(float4*)(Mp + (b0 + 1) * 24 + m0) = make_float4(acc[4], acc[5], acc[6], acc[7]);
    }

    // noise2 -> mlp_in[b][16..23]
    {
        const int b = lane >> 1;
        const int j = (lane & 1) * 4;
        float4 v = *(const float4*)(nz2 + (b * NPIXC + p) * 8 + j);
        *(float4*)(Mp + b * 24 + 16 + j) = v;
    }
    __syncwarp();

    // MLP: lane = b*2 + half ; each half handles 32 hidden units, h kept in regs,
    // out accumulated incrementally, pair-reduced via shfl.
    {
        const int b    = lane >> 1;
        const int half = lane & 1;

        float r[24];
        #pragma unroll
        for (int d4 = 0; d4 < 6; ++d4) {
            float4 v = *(const float4*)(Mp + b * 24 + d4 * 4);
            r[d4 * 4 + 0] = v.x; r[d4 * 4 + 1] = v.y;
            r[d4 * 4 + 2] = v.z; r[d4 * 4 + 3] = v.w;
        }

        float o[8];
        #pragma unroll
        for (int f = 0; f < 8; ++f) o[f] = 0.f;

        const int ibase = half * 32;
        #pragma unroll 4
        for (int ii = 0; ii < 32; ++ii) {
            const int i = ibase + ii;
            const float* wr = sW1 + i * 24;
            float a = sB1[i];
            #pragma unroll
            for (int d4 = 0; d4 < 6; ++d4) {
                float4 w = *(const float4*)(wr + d4 * 4);
                a = fmaf(w.x, r[d4 * 4 + 0], a);
                a = fmaf(w.y, r[d4 * 4 + 1], a);
                a = fmaf(w.z, r[d4 * 4 + 2], a);
                a = fmaf(w.w, r[d4 * 4 + 3], a);
            }
            a = fmaxf(a, 0.f);
            float4 wa = *(const float4*)(sW2 + i * 8);
            float4 wb = *(const float4*)(sW2 + i * 8 + 4);
            o[0] = fmaf(a, wa.x, o[0]); o[1] = fmaf(a, wa.y, o[1]);
            o[2] = fmaf(a, wa.z, o[2]); o[3] = fmaf(a, wa.w, o[3]);
            o[4] = fmaf(a, wb.x, o[4]); o[5] = fmaf(a, wb.y, o[5]);
            o[6] = fmaf(a, wb.z, o[6]); o[7] = fmaf(a, wb.w, o[7]);
        }

        #pragma unroll
        for (int f = 0; f < 8; ++f) {
            float a = o[f] + __shfl_xor_sync(0xffffffffu, o[f], 1);
            o[f] = a + sB2[f];
        }
        if (half == 0) {
            #pragma unroll
            for (int f = 0; f < 8; ++f)
                sO[(b * 8 + f) * 8 + px] = o[f];
        }
    }
    __syncthreads();

    // ---- coalesced output write: out[b][f][p0..p0+7] ----
    {
        const int bf = tid >> 1;        // 0..127 == b*8+f
        const int qq = tid & 1;
        float4 v = *(const float4*)(sO + bf * 8 + qq * 4);
        *(float4*)(out + bf * NPIXC + p0 + qq * 4) = v;
    }
}

extern "C" void kernel_launch(void* const* d_in, const int* in_sizes, int n_in,
                              void* d_out, int out_size)
{
    const float* y    = (const float*)d_in[0];
    const float* nz   = (const float*)d_in[1];
    const float* nz2  = (const float*)d_in[2];
    const float* wmap = (const float*)d_in[3];
    const float* w1   = (const float*)d_in[4];
    const float* b1   = (const float*)d_in[5];
    const float* w2   = (const float*)d_in[6];
    const float* b2   = (const float*)d_in[7];
    const int*   nidx = (const int*)d_in[8];
    float* out = (float*)d_out;

    cudaFuncSetAttribute(lr_kernel, cudaFuncAttributeMaxDynamicSharedMemorySize, SMEM_BYTES);
    lr_kernel<<<NPIXC / PXB, THREADS, SMEM_BYTES>>>(y, nz, nz2, wmap, w1, b1, w2, b2, nidx, out);
}

// round 2
// speedup vs baseline: 2.1188x; 2.1188x over previous
#include <cuda_runtime.h>

#define NPIXC   16384
#define PXB     4          // pixels per block (1 per warp)
#define THREADS 128

// shared memory layout (float offsets)
#define GSTR    2308                    // per-pixel gathered feats [b][k][n], padded
#define MSTR    28                      // mlp_in row stride (24 padded)
#define MPX     448                     // 16*28 per pixel
#define OFF_G   0                       // 4*2308 = 9232
#define OFF_M   9232                    // 4*448  = 1792
#define OFF_W1  11024                   // 64*24  = 1536
#define OFF_B1  12560                   // 64
#define OFF_W2T 12624                   // 64*8   = 512 (transposed w2)
#define OFF_B2  13136                   // 8
#define OFF_O   13144                   // 128*4  = 512
#define OFF_N   13656                   // 36 ints
#define SMEM_FLOATS 13692
#define SMEM_BYTES (SMEM_FLOATS * 4)

__global__ void __launch_bounds__(THREADS)
lr_kernel(const float* __restrict__ y,     // [16][8][NPIX]
          const float* __restrict__ nz,    // [16][8][NPIX]
          const float* __restrict__ nz2,   // [16][NPIX][8]
          const float* __restrict__ wmap,  // [NPIX][9][16][16]
          const float* __restrict__ w1,    // [64][24]
          const float* __restrict__ b1,    // [64]
          const float* __restrict__ w2,    // [8][64]
          const float* __restrict__ b2,    // [8]
          const int*   __restrict__ nidx,  // [NPIX][9]
          float*       __restrict__ out)   // [16][8][NPIX]
{
    extern __shared__ float s[];
    float* sG  = s + OFF_G;
    float* sM  = s + OFF_M;
    float* sW1 = s + OFF_W1;
    float* sB1 = s + OFF_B1;
    float* sW2 = s + OFF_W2T;
    float* sB2 = s + OFF_B2;
    float* sO  = s + OFF_O;
    int*   sN  = (int*)(s + OFF_N);

    const int tid = threadIdx.x;
    const int p0  = blockIdx.x * PXB;

    // ---- small shared weights + neighbor indices ----
    for (int i = tid; i < 1536; i += THREADS) sW1[i] = w1[i];
    if (tid < 64) sB1[tid] = b1[tid];
    for (int i = tid; i < 512; i += THREADS)              // sW2[i][f]
        sW2[i] = w2[(i & 7) * 64 + (i >> 3)];
    if (tid < 8) sB2[tid] = b2[tid];
    if (tid < 36) sN[tid] = nidx[p0 * 9 + tid];
    __syncthreads();

    // ---- gather features into sG[px][b][k][n] ----
    {
        const int px = tid & 3;
        const int fo = tid >> 2;            // 0..31
        float* gpx = sG + px * GSTR;
        #pragma unroll 4
        for (int it = 0; it < 72; ++it) {
            int f = it * 32 + fo;           // over 2304 = (b,k,n)
            int n = f & 15;
            int k = (f >> 4) % 9;
            int b = f / 144;
            int q = sN[px * 9 + k];
            const float* src = (n < 8) ? y : nz;
            gpx[(b * 9 + k) * 16 + n] = src[(b * 8 + (n & 7)) * NPIXC + q];
        }
    }
    __syncthreads();

    // ---- per-warp einsum: one pixel, W streamed to registers ----
    const int lane = tid & 31;
    const int px   = tid >> 5;
    const int p    = p0 + px;
    const float* Gp = sG + px * GSTR;
    float* Mp = sM + px * MPX;

    {
        const int mp = lane >> 2;          // m pair 0..7
        const int nq = lane & 3;           // n quarter 0..3
        const float* wp = wmap + (size_t)p * 2304 + (2 * mp) * 16 + nq * 4;

        float acc[16][2];
        #pragma unroll
        for (int b = 0; b < 16; ++b) { acc[b][0] = 0.f; acc[b][1] = 0.f; }

        float4 wa0 = *(const float4*)(wp);
        float4 wa1 = *(const float4*)(wp + 16);

        #pragma unroll
        for (int k = 0; k < 9; ++k) {
            int kn = (k < 8) ? (k + 1) : k;     // safe re-read on last iter
            float4 wb0 = *(const float4*)(wp + kn * 256);
            float4 wb1 = *(const float4*)(wp + kn * 256 + 16);

            const float* gk = Gp + k * 16 + nq * 4;
            #pragma unroll
            for (int b = 0; b < 16; ++b) {
                float4 g = *(const float4*)(gk + b * 144);
                float a0 = acc[b][0], a1 = acc[b][1];
                a0 = fmaf(g.x, wa0.x, a0); a1 = fmaf(g.x, wa1.x, a1);
                a0 = fmaf(g.y, wa0.y, a0); a1 = fmaf(g.y, wa1.y, a1);
                a0 = fmaf(g.z, wa0.z, a0); a1 = fmaf(g.z, wa1.z, a1);
                a0 = fmaf(g.w, wa0.w, a0); a1 = fmaf(g.w, wa1.w, a1);
                acc[b][0] = a0; acc[b][1] = a1;
            }
            wa0 = wb0; wa1 = wb1;
        }

        // reduce over the 4 n-quarter lanes
        #pragma unroll
        for (int b = 0; b < 16; ++b) {
            #pragma unroll
            for (int mi = 0; mi < 2; ++mi) {
                float v = acc[b][mi];
                v += __shfl_xor_sync(0xffffffffu, v, 1);
                v += __shfl_xor_sync(0xffffffffu, v, 2);
                acc[b][mi] = v;
            }
        }
        // lane nq writes batches {nq, nq+4, nq+8, nq+12}
        #pragma unroll
        for (int j = 0; j < 4; ++j) {
            int b = nq + j * 4;
            Mp[b * MSTR + 2 * mp + 0] = acc[b][0];
            Mp[b * MSTR + 2 * mp + 1] = acc[b][1];
        }
    }

    // noise2 -> mlp_in[b][16..23]
    {
        const int b = lane >> 1;
        const int j = (lane & 1) * 4;
        float4 v = *(const float4*)(nz2 + ((size_t)b * NPIXC + p) * 8 + j);
        *(float4*)(Mp + b * MSTR + 16 + j) = v;
    }
    __syncwarp();

    // ---- fused MLP: lane = b*2 + half ----
    {
        const int b    = lane >> 1;
        const int half = lane & 1;

        float r[24];
        #pragma unroll
        for (int d4 = 0; d4 < 6; ++d4) {
            float4 v = *(const float4*)(Mp + b * MSTR + d4 * 4);
            r[d4 * 4 + 0] = v.x; r[d4 * 4 + 1] = v.y;
            r[d4 * 4 + 2] = v.z; r[d4 * 4 + 3] = v.w;
        }

        float o[8];
        #pragma unroll
        for (int f = 0; f < 8; ++f) o[f] = 0.f;

        const int ibase = half * 32;
        #pragma unroll 4
        for (int ii = 0; ii < 32; ++ii) {
            const int i = ibase + ii;
            const float* wr = sW1 + i * 24;
            float a = sB1[i];
            #pragma unroll
            for (int d4 = 0; d4 < 6; ++d4) {
                float4 w = *(const float4*)(wr + d4 * 4);
                a = fmaf(w.x, r[d4 * 4 + 0], a);
                a = fmaf(w.y, r[d4 * 4 + 1], a);
                a = fmaf(w.z, r[d4 * 4 + 2], a);
                a = fmaf(w.w, r[d4 * 4 + 3], a);
            }
            a = fmaxf(a, 0.f);
            float4 wa = *(const float4*)(sW2 + i * 8);
            float4 wb = *(const float4*)(sW2 + i * 8 + 4);
            o[0] = fmaf(a, wa.x, o[0]); o[1] = fmaf(a, wa.y, o[1]);
            o[2] = fmaf(a, wa.z, o[2]); o[3] = fmaf(a, wa.w, o[3]);
            o[4] = fmaf(a, wb.x, o[4]); o[5] = fmaf(a, wb.y, o[5]);
            o[6] = fmaf(a, wb.z, o[6]); o[7] = fmaf(a, wb.w, o[7]);
        }

        #pragma unroll
        for (int f = 0; f < 8; ++f) {
            float a = o[f] + __shfl_xor_sync(0xffffffffu, o[f], 1);
            o[f] = a + sB2[f];
        }
        if (half == 0) {
            #pragma unroll
            for (int f = 0; f < 8; ++f)
                sO[(b * 8 + f) * 4 + px] = o[f];
        }
    }
    __syncthreads();

    // ---- coalesced-ish output: out[b][f][p0..p0+3] ----
    {
        float4 v = *(const float4*)(sO + tid * 4);
        *(float4*)(out + (size_t)tid * NPIXC + p0) = v;
    }
}

extern "C" void kernel_launch(void* const* d_in, const int* in_sizes, int n_in,
                              void* d_out, int out_size)
{
    const float* y    = (const float*)d_in[0];
    const float* nz   = (const float*)d_in[1];
    const float* nz2  = (const float*)d_in[2];
    const float* wmap = (const float*)d_in[3];
    const float* w1   = (const float*)d_in[4];
    const float* b1   = (const float*)d_in[5];
    const float* w2   = (const float*)d_in[6];
    const float* b2   = (const float*)d_in[7];
    const int*   nidx = (const int*)d_in[8];
    float* out = (float*)d_out;

    cudaFuncSetAttribute(lr_kernel, cudaFuncAttributeMaxDynamicSharedMemorySize, SMEM_BYTES);
    lr_kernel<<<NPIXC / PXB, THREADS, SMEM_BYTES>>>(y, nz, nz2, wmap, w1, b1, w2, b2, nidx, out);
}

// round 3
// speedup vs baseline: 4.3710x; 2.0630x over previous
#include <cuda_runtime.h>
#include <cstdint>

#define NPIXC   16384
#define PXB     4
#define THREADS 128

// shared memory word offsets
#define ASTR    2312
#define OFF_A   0            // 4*2312 = 9248  (einsum A-frags; reused for H-frags)
#define MSTR    384
#define OFF_M   9248         // 4*384 = 1536   (mlp_in A-frags)
#define OFF_W1F 10784        // 1536           (w1 B-frags, tf32)
#define OFF_B1  12320        // 64
#define OFF_W2F 12384        // 512            (w2 B-frags, tf32)
#define OFF_B2  12896        // 8
#define OFF_O   12904        // 512
#define OFF_N   13416        // 36
#define SMEM_WORDS 13452
#define SMEM_BYTES (SMEM_WORDS * 4)

__device__ __forceinline__ uint32_t cvt_tf32(float x) {
    uint32_t r;
    asm("cvt.rna.tf32.f32 %0, %1;" : "=r"(r) : "f"(x));
    return r;
}

__device__ __forceinline__ void mma_tf32(float* d, const uint32_t* a, uint32_t b0, uint32_t b1) {
    asm("mma.sync.aligned.m16n8k8.row.col.f32.tf32.tf32.f32 "
        "{%0,%1,%2,%3}, {%4,%5,%6,%7}, {%8,%9}, {%0,%1,%2,%3};"
        : "+f"(d[0]), "+f"(d[1]), "+f"(d[2]), "+f"(d[3])
        : "r"(a[0]), "r"(a[1]), "r"(a[2]), "r"(a[3]), "r"(b0), "r"(b1));
}

// fragment slot for an A-operand element (row r, col c) within one m16n8k8 tile:
// word = lane'*4 + reg ; lane' = (r&7)*4 + (c&3) ; reg = (r>>3) + 2*((c>>2)&1)
__device__ __forceinline__ int fragslot(int r, int c) {
    return ((r & 7) * 4 + (c & 3)) * 4 + (r >> 3) + 2 * ((c >> 2) & 1);
}

__global__ void __launch_bounds__(THREADS)
lr_kernel(const float* __restrict__ y,     // [16][8][NPIX]
          const float* __restrict__ nz,    // [16][8][NPIX]
          const float* __restrict__ nz2,   // [16][NPIX][8]
          const float* __restrict__ wmap,  // [NPIX][9][16][16]
          const float* __restrict__ w1,    // [64][24]
          const float* __restrict__ b1,    // [64]
          const float* __restrict__ w2,    // [8][64]
          const float* __restrict__ b2,    // [8]
          const int*   __restrict__ nidx,  // [NPIX][9]
          float*       __restrict__ out)   // [16][8][NPIX]
{
    extern __shared__ uint32_t su[];
    uint32_t* sA   = su + OFF_A;
    uint32_t* sM   = su + OFF_M;
    uint32_t* sW1f = su + OFF_W1F;
    float*    sB1f = (float*)(su + OFF_B1);
    uint32_t* sW2f = su + OFF_W2F;
    float*    sB2f = (float*)(su + OFF_B2);
    float*    sOf  = (float*)(su + OFF_O);
    int*      sN   = (int*)(su + OFF_N);

    const int tid = threadIdx.x;
    const int p0  = blockIdx.x * PXB;

    // ---- setup: fragment-ordered tf32 weights + biases + neighbor idx ----
    #pragma unroll
    for (int s = tid; s < 1536; s += THREADS) {          // w1^T B-frags [j8][kt3][l32][rg2]
        int j = s / 192, r = s - j * 192;
        int kt = r >> 6, r2 = r & 63, l = r2 >> 1, rg = r2 & 1;
        int d = kt * 8 + (l & 3) + rg * 4;
        int i = j * 8 + (l >> 2);
        sW1f[s] = cvt_tf32(w1[i * 24 + d]);
    }
    #pragma unroll
    for (int s = tid; s < 512; s += THREADS) {           // w2^T B-frags [kt8][l32][rg2]
        int kt = s >> 6, r2 = s & 63, l = r2 >> 1, rg = r2 & 1;
        int row = kt * 8 + (l & 3) + 4 * rg;             // h index
        int col = l >> 2;                                // f index
        sW2f[s] = cvt_tf32(w2[col * 64 + row]);
    }
    if (tid < 64) sB1f[tid] = b1[tid];
    if (tid < 8)  sB2f[tid] = b2[tid];
    if (tid < 36) sN[tid] = nidx[p0 * 9 + tid];
    __syncthreads();

    // ---- gather: write G straight into A-fragment layout (tf32) ----
    {
        const int gpx = tid & 3;
        const int fo  = tid >> 2;            // 0..31
        const int n   = fo & 15;
        const int blo = fo >> 4;             // 0..1
        int qk[9];
        #pragma unroll
        for (int k = 0; k < 9; ++k) qk[k] = sN[gpx * 9 + k];
        const float* src = (n < 8) ? (y + (size_t)n * NPIXC)
                                   : (nz + (size_t)(n - 8) * NPIXC);
        uint32_t* sAp = sA + gpx * ASTR;
        const int nconst = 128 * (n >> 3) + 4 * (n & 3) + 2 * ((n >> 2) & 1);
        #pragma unroll
        for (int bo = 0; bo < 8; ++bo) {
            int b = bo * 2 + blo;
            const float* sb = src + (size_t)b * 8 * NPIXC;
            int bs = nconst + 16 * (b & 7) + (b >> 3);
            #pragma unroll
            for (int k = 0; k < 9; ++k)
                sAp[bs + k * 256] = cvt_tf32(__ldg(sb + qk[k]));
        }
    }
    __syncthreads();

    // ---- per-warp pixel ----
    const int l  = tid & 31;
    const int px = tid >> 5;
    const int p  = p0 + px;
    uint32_t* sAp = sA + px * ASTR;
    uint32_t* sMp = sM + px * MSTR;

    // einsum: D1[16b x 16m] = G[16 x 144] * W[144 x 16]
    float d0[4] = {0.f, 0.f, 0.f, 0.f};
    float d1[4] = {0.f, 0.f, 0.f, 0.f};
    {
        const float* wp = wmap + (size_t)p * 2304 + (l >> 2) * 16 + (l & 3);
        #pragma unroll
        for (int t = 0; t < 18; ++t) {
            uint4 av = *(const uint4*)(sAp + t * 128 + l * 4);
            uint32_t a[4] = {av.x, av.y, av.z, av.w};
            const float* wt = wp + (t >> 1) * 256 + (t & 1) * 8;
            uint32_t b00 = cvt_tf32(__ldg(wt + 0));
            uint32_t b01 = cvt_tf32(__ldg(wt + 4));
            uint32_t b10 = cvt_tf32(__ldg(wt + 128));
            uint32_t b11 = cvt_tf32(__ldg(wt + 132));
            mma_tf32(d0, a, b00, b01);
            mma_tf32(d1, a, b10, b11);
        }
    }

    // stage mlp_in = [D1 | noise2] into A-frag layout (kt = d>>3)
    {
        int r = l >> 2, c = 2 * (l & 3);
        sMp[0 * 128 * 0 + (c >> 3) * 128 + fragslot(r, c)]             = cvt_tf32(d0[0]);
        sMp[((c + 1) >> 3) * 128 + fragslot(r, c + 1)]                 = cvt_tf32(d0[1]);
        sMp[(c >> 3) * 128 + fragslot(r + 8, c)]                       = cvt_tf32(d0[2]);
        sMp[((c + 1) >> 3) * 128 + fragslot(r + 8, c + 1)]             = cvt_tf32(d0[3]);
        int c8 = c + 8;
        sMp[(c8 >> 3) * 128 + fragslot(r, c8)]                         = cvt_tf32(d1[0]);
        sMp[((c8 + 1) >> 3) * 128 + fragslot(r, c8 + 1)]               = cvt_tf32(d1[1]);
        sMp[(c8 >> 3) * 128 + fragslot(r + 8, c8)]                     = cvt_tf32(d1[2]);
        sMp[((c8 + 1) >> 3) * 128 + fragslot(r + 8, c8 + 1)]           = cvt_tf32(d1[3]);

        int b  = l >> 1;
        int qo = (l & 1) * 4;
        float4 v = *(const float4*)(nz2 + ((size_t)b * NPIXC + p) * 8 + qo);
        sMp[2 * 128 + fragslot(b, (16 + qo + 0) & 7)] = cvt_tf32(v.x);
        sMp[2 * 128 + fragslot(b, (16 + qo + 1) & 7)] = cvt_tf32(v.y);
        sMp[2 * 128 + fragslot(b, (16 + qo + 2) & 7)] = cvt_tf32(v.z);
        sMp[2 * 128 + fragslot(b, (16 + qo + 3) & 7)] = cvt_tf32(v.w);
    }
    __syncwarp();

    // GEMM2: H[16 x 64] = M[16 x 24] * w1^T[24 x 64]
    float h[8][4];
    #pragma unroll
    for (int j = 0; j < 8; ++j) { h[j][0] = h[j][1] = h[j][2] = h[j][3] = 0.f; }
    #pragma unroll
    for (int kt = 0; kt < 3; ++kt) {
        uint4 av = *(const uint4*)(sMp + kt * 128 + l * 4);
        uint32_t a[4] = {av.x, av.y, av.z, av.w};
        #pragma unroll
        for (int j = 0; j < 8; ++j) {
            uint2 bf = *(const uint2*)(sW1f + (j * 3 + kt) * 64 + l * 2);
            mma_tf32(h[j], a, bf.x, bf.y);
        }
    }

    // bias + relu, restage H as A-frags for GEMM3 (reuse sA px region)
    uint32_t* sHp = sAp;
    {
        int r = l >> 2, c0 = 2 * (l & 3);
        #pragma unroll
        for (int j = 0; j < 8; ++j) {
            float ba = sB1f[8 * j + c0], bb = sB1f[8 * j + c0 + 1];
            float v0 = fmaxf(h[j][0] + ba, 0.f);
            float v1 = fmaxf(h[j][1] + bb, 0.f);
            float v2 = fmaxf(h[j][2] + ba, 0.f);
            float v3 = fmaxf(h[j][3] + bb, 0.f);
            sHp[j * 128 + fragslot(r,     c0)]     = cvt_tf32(v0);
            sHp[j * 128 + fragslot(r,     c0 + 1)] = cvt_tf32(v1);
            sHp[j * 128 + fragslot(r + 8, c0)]     = cvt_tf32(v2);
            sHp[j * 128 + fragslot(r + 8, c0 + 1)] = cvt_tf32(v3);
        }
    }
    __syncwarp();

    // GEMM3: OUT[16 x 8] = H[16 x 64] * w2^T[64 x 8]
    float o[4] = {0.f, 0.f, 0.f, 0.f};
    #pragma unroll
    for (int kt = 0; kt < 8; ++kt) {
        uint4 av = *(const uint4*)(sHp + kt * 128 + l * 4);
        uint32_t a[4] = {av.x, av.y, av.z, av.w};
        uint2 bf = *(const uint2*)(sW2f + kt * 64 + l * 2);
        mma_tf32(o, a, bf.x, bf.y);
    }
    {
        int f0 = 2 * (l & 3);
        int b0i = l >> 2;
        o[0] += sB2f[f0];
        o[1] += sB2f[f0 + 1];
        o[2] += sB2f[f0];
        o[3] += sB2f[f0 + 1];
        sOf[(b0i * 8 + f0) * 4 + px]           = o[0];
        sOf[(b0i * 8 + f0 + 1) * 4 + px]       = o[1];
        sOf[((b0i + 8) * 8 + f0) * 4 + px]     = o[2];
        sOf[((b0i + 8) * 8 + f0 + 1) * 4 + px] = o[3];
    }
    __syncthreads();

    // coalesced output: out[bf][p0..p0+3]
    {
        float4 v = *(const float4*)(sOf + tid * 4);
        *(float4*)(out + (size_t)tid * NPIXC + p0) = v;
    }
}

extern "C" void kernel_launch(void* const* d_in, const int* in_sizes, int n_in,
                              void* d_out, int out_size)
{
    const float* y    = (const float*)d_in[0];
    const float* nz   = (const float*)d_in[1];
    const float* nz2  = (const float*)d_in[2];
    const float* wmap = (const float*)d_in[3];
    const float* w1   = (const float*)d_in[4];
    const float* b1   = (const float*)d_in[5];
    const float* w2   = (const float*)d_in[6];
    const float* b2   = (const float*)d_in[7];
    const int*   nidx = (const int*)d_in[8];
    float* out = (float*)d_out;

    cudaFuncSetAttribute(lr_kernel, cudaFuncAttributeMaxDynamicSharedMemorySize, SMEM_BYTES);
    lr_kernel<<<NPIXC / PXB, THREADS, SMEM_BYTES>>>(y, nz, nz2, wmap, w1, b1, w2, b2, nidx, out);
}

// round 4
// speedup vs baseline: 5.1878x; 1.1869x over previous
#include <cuda_runtime.h>
#include <cstdint>

#define NPIXC   16384
#define PXB     8
#define THREADS 256
#define PXS     772        // per-pixel chunk-buffer stride (768 + 4 pad)
#define BUFW    (PXB*PXS)  // 6176

// shared memory word offsets
#define OFF_A    0                 // 2*6176 = 12352 (double-buffered G chunks; reused for H)
#define OFF_M    12352             // 8*384 = 3072 (mlp_in A-frags)
#define OFF_W1F  15424             // 1536
#define OFF_B1   16960             // 64
#define OFF_W2F  17024             // 512
#define OFF_B2   17536             // 8
#define OFF_O    17544             // 1024
#define OFF_N    18568             // 72
#define SMEM_WORDS 18640
#define SMEM_BYTES (SMEM_WORDS * 4)

__device__ __forceinline__ uint32_t cvt_tf32(float x) {
    uint32_t r;
    asm("cvt.rna.tf32.f32 %0, %1;" : "=r"(r) : "f"(x));
    return r;
}

__device__ __forceinline__ void mma_tf32(float* d, const uint32_t* a, uint32_t b0, uint32_t b1) {
    asm("mma.sync.aligned.m16n8k8.row.col.f32.tf32.tf32.f32 "
        "{%0,%1,%2,%3}, {%4,%5,%6,%7}, {%8,%9}, {%0,%1,%2,%3};"
        : "+f"(d[0]), "+f"(d[1]), "+f"(d[2]), "+f"(d[3])
        : "r"(a[0]), "r"(a[1]), "r"(a[2]), "r"(a[3]), "r"(b0), "r"(b1));
}

// A-fragment word slot for element (row r, col c) of one m16n8k8 tile
// word = ((r&7)*4 + (c&3))*4 + (r>>3) + 2*((c>>2)&1)   [validated in R3]
__device__ __forceinline__ int fragslot(int r, int c) {
    return ((r & 7) * 4 + (c & 3)) * 4 + (r >> 3) + 2 * ((c >> 2) & 1);
}

__global__ void __launch_bounds__(THREADS, 3)
lr_kernel(const float* __restrict__ y,     // [16][8][NPIX]
          const float* __restrict__ nz,    // [16][8][NPIX]
          const float* __restrict__ nz2,   // [16][NPIX][8]
          const float* __restrict__ wmap,  // [NPIX][9][16][16]
          const float* __restrict__ w1,    // [64][24]
          const float* __restrict__ b1,    // [64]
          const float* __restrict__ w2,    // [8][64]
          const float* __restrict__ b2,    // [8]
          const int*   __restrict__ nidx,  // [NPIX][9]
          float*       __restrict__ out)   // [16][8][NPIX]
{
    extern __shared__ uint32_t su[];
    uint32_t* sA   = su + OFF_A;
    uint32_t* sM   = su + OFF_M;
    uint32_t* sW1f = su + OFF_W1F;
    float*    sB1f = (float*)(su + OFF_B1);
    uint32_t* sW2f = su + OFF_W2F;
    float*    sB2f = (float*)(su + OFF_B2);
    float*    sOf  = (float*)(su + OFF_O);
    int*      sN   = (int*)(su + OFF_N);

    const int tid = threadIdx.x;
    const int p0  = blockIdx.x * PXB;

    // ---- setup: fragment-ordered tf32 MLP weights + biases + neighbor idx ----
    for (int s = tid; s < 1536; s += THREADS) {          // w1^T B-frags [j8][kt3][l32][rg2]
        int j = s / 192, r = s - j * 192;
        int kt = r >> 6, r2 = r & 63, l = r2 >> 1, rg = r2 & 1;
        int d = kt * 8 + (l & 3) + rg * 4;
        int i = j * 8 + (l >> 2);
        sW1f[s] = cvt_tf32(w1[i * 24 + d]);
    }
    for (int s = tid; s < 512; s += THREADS) {           // w2^T B-frags [kt8][l32][rg2]
        int kt = s >> 6, r2 = s & 63, l = r2 >> 1, rg = r2 & 1;
        int row = kt * 8 + (l & 3) + 4 * rg;
        int col = l >> 2;
        sW2f[s] = cvt_tf32(w2[col * 64 + row]);
    }
    if (tid < 64) sB1f[tid] = b1[tid];
    if (tid < 8)  sB2f[tid] = b2[tid];
    if (tid < 72) sN[tid] = nidx[p0 * 9 + tid];
    __syncthreads();

    // ---- gather geometry (per thread, fixed) ----
    const int gpx = tid & 7;           // pixel
    const int fo  = tid >> 3;          // 0..31
    const int b7  = fo & 7;            // low batch index
    const int nh  = fo >> 3;           // n quarter 0..3 (n = nh*4 + i)
    const float* gsrc = ((nh < 2) ? y : nz)
                      + (size_t)((nh & 1) * 4) * NPIXC
                      + (size_t)b7 * 8 * NPIXC;
    // store offset (within a buffer): gpx*PXS + 16*b7 + 128*(nh>>1) + k'*256 + nmix(i)
    const int gsto = gpx * PXS + 16 * b7 + 128 * (nh >> 1);

    // ---- prologue: gather chunk 0 into buffer 0 ----
    {
        uint32_t* dst = sA + gsto;
        #pragma unroll
        for (int kk = 0; kk < 3; ++kk) {
            int q = sN[gpx * 9 + kk];
            #pragma unroll
            for (int i = 0; i < 4; ++i) {
                const float* a = gsrc + (size_t)i * NPIXC + q;
                float lo = __ldg(a);
                float hi = __ldg(a + 64 * NPIXC);
                int off = kk * 256 + 4 * ((2 * nh + (i >> 1)) & 3) + 2 * (i & 1);
                *(uint2*)(dst + off) = make_uint2(cvt_tf32(lo), cvt_tf32(hi));
            }
        }
    }
    __syncthreads();

    // ---- main loop: einsum chunks with prefetched gather ----
    const int l  = tid & 31;
    const int px = tid >> 5;
    const int p  = p0 + px;

    float d0[4] = {0.f, 0.f, 0.f, 0.f};
    float d1[4] = {0.f, 0.f, 0.f, 0.f};
    const float* wp = wmap + (size_t)p * 2304 + (l >> 2) * 16 + 2 * (l & 3);

    float g[24];
    #pragma unroll 1
    for (int c = 0; c < 3; ++c) {
        // prefetch next chunk's gather values into registers
        if (c < 2) {
            #pragma unroll
            for (int kk = 0; kk < 3; ++kk) {
                int q = sN[gpx * 9 + (c + 1) * 3 + kk];
                #pragma unroll
                for (int i = 0; i < 4; ++i) {
                    const float* a = gsrc + (size_t)i * NPIXC + q;
                    g[kk * 8 + i * 2]     = __ldg(a);
                    g[kk * 8 + i * 2 + 1] = __ldg(a + 64 * NPIXC);
                }
            }
        }
        // einsum on chunk c (buffer c&1): 6 tiles, 12 MMAs
        {
            const uint32_t* abuf = sA + (c & 1) * BUFW + px * PXS;
            const float* wc = wp + (size_t)c * 768;
            #pragma unroll
            for (int kk = 0; kk < 3; ++kk) {
                #pragma unroll
                for (int h = 0; h < 2; ++h) {
                    uint4 av = *(const uint4*)(abuf + kk * 256 + h * 128 + l * 4);
                    const float* wt = wc + kk * 256 + h * 8;
                    float2 w0 = *(const float2*)(wt);
                    float2 w1v = *(const float2*)(wt + 128);
                    uint32_t a[4] = {av.x, av.y, av.z, av.w};
                    mma_tf32(d0, a, cvt_tf32(w0.x), cvt_tf32(w0.y));
                    mma_tf32(d1, a, cvt_tf32(w1v.x), cvt_tf32(w1v.y));
                }
            }
        }
        // commit prefetched gather into the other buffer
        if (c < 2) {
            uint32_t* dst = sA + ((c + 1) & 1) * BUFW + gsto;
            #pragma unroll
            for (int kk = 0; kk < 3; ++kk) {
                #pragma unroll
                for (int i = 0; i < 4; ++i) {
                    int off = kk * 256 + 4 * ((2 * nh + (i >> 1)) & 3) + 2 * (i & 1);
                    *(uint2*)(dst + off) = make_uint2(cvt_tf32(g[kk * 8 + i * 2]),
                                                      cvt_tf32(g[kk * 8 + i * 2 + 1]));
                }
            }
        }
        __syncthreads();
    }

    // ---- stage mlp_in = [D1 | noise2] into A-frag layout ----
    uint32_t* sMp = sM + px * 384;
    {
        int r = l >> 2, cc = 2 * (l & 3);
        sMp[(cc >> 3) * 128 + fragslot(r, cc)]                 = cvt_tf32(d0[0]);
        sMp[((cc + 1) >> 3) * 128 + fragslot(r, cc + 1)]       = cvt_tf32(d0[1]);
        sMp[(cc >> 3) * 128 + fragslot(r + 8, cc)]             = cvt_tf32(d0[2]);
        sMp[((cc + 1) >> 3) * 128 + fragslot(r + 8, cc + 1)]   = cvt_tf32(d0[3]);
        int c8 = cc + 8;
        sMp[(c8 >> 3) * 128 + fragslot(r, c8)]                 = cvt_tf32(d1[0]);
        sMp[((c8 + 1) >> 3) * 128 + fragslot(r, c8 + 1)]       = cvt_tf32(d1[1]);
        sMp[(c8 >> 3) * 128 + fragslot(r + 8, c8)]             = cvt_tf32(d1[2]);
        sMp[((c8 + 1) >> 3) * 128 + fragslot(r + 8, c8 + 1)]   = cvt_tf32(d1[3]);

        int b  = l >> 1;
        int qo = (l & 1) * 4;
        float4 v = *(const float4*)(nz2 + ((size_t)b * NPIXC + p) * 8 + qo);
        sMp[2 * 128 + fragslot(b, qo + 0)] = cvt_tf32(v.x);
        sMp[2 * 128 + fragslot(b, qo + 1)] = cvt_tf32(v.y);
        sMp[2 * 128 + fragslot(b, qo + 2)] = cvt_tf32(v.z);
        sMp[2 * 128 + fragslot(b, qo + 3)] = cvt_tf32(v.w);
    }
    __syncwarp();

    // ---- GEMM2: H[16x64] = M[16x24] * w1^T[24x64] ----
    float h[8][4];
    #pragma unroll
    for (int j = 0; j < 8; ++j) { h[j][0] = h[j][1] = h[j][2] = h[j][3] = 0.f; }
    #pragma unroll
    for (int kt = 0; kt < 3; ++kt) {
        uint4 av = *(const uint4*)(sMp + kt * 128 + l * 4);
        uint32_t a[4] = {av.x, av.y, av.z, av.w};
        #pragma unroll
        for (int j = 0; j < 8; ++j) {
            uint2 bf = *(const uint2*)(sW1f + (j * 3 + kt) * 64 + l * 2);
            mma_tf32(h[j], a, bf.x, bf.y);
        }
    }

    // bias + relu, restage H as A-frags (reuse sA region)
    uint32_t* sHp = sA + px * 1024;
    {
        int r = l >> 2, c0 = 2 * (l & 3);
        #pragma unroll
        for (int j = 0; j < 8; ++j) {
            float ba = sB1f[8 * j + c0], bb = sB1f[8 * j + c0 + 1];
            float v0 = fmaxf(h[j][0] + ba, 0.f);
            float v1 = fmaxf(h[j][1] + bb, 0.f);
            float v2 = fmaxf(h[j][2] + ba, 0.f);
            float v3 = fmaxf(h[j][3] + bb, 0.f);
            sHp[j * 128 + fragslot(r,     c0)]     = cvt_tf32(v0);
            sHp[j * 128 + fragslot(r,     c0 + 1)] = cvt_tf32(v1);
            sHp[j * 128 + fragslot(r + 8, c0)]     = cvt_tf32(v2);
            sHp[j * 128 + fragslot(r + 8, c0 + 1)] = cvt_tf32(v3);
        }
    }
    __syncwarp();

    // ---- GEMM3: OUT[16x8] = H[16x64] * w2^T[64x8] ----
    float o[4] = {0.f, 0.f, 0.f, 0.f};
    #pragma unroll
    for (int kt = 0; kt < 8; ++kt) {
        uint4 av = *(const uint4*)(sHp + kt * 128 + l * 4);
        uint32_t a[4] = {av.x, av.y, av.z, av.w};
        uint2 bf = *(const uint2*)(sW2f + kt * 64 + l * 2);
        mma_tf32(o, a, bf.x, bf.y);
    }
    {
        int f0  = 2 * (l & 3);
        int b0i = l >> 2;
        o[0] += sB2f[f0];
        o[1] += sB2f[f0 + 1];
        o[2] += sB2f[f0];
        o[3] += sB2f[f0 + 1];
        sOf[(b0i * 8 + f0) * 8 + px]             = o[0];
        sOf[(b0i * 8 + f0 + 1) * 8 + px]         = o[1];
        sOf[((b0i + 8) * 8 + f0) * 8 + px]       = o[2];
        sOf[((b0i + 8) * 8 + f0 + 1) * 8 + px]   = o[3];
    }
    __syncthreads();

    // ---- coalesced output: out[bf][p0..p0+7] ----
    {
        float4 v = *(const float4*)(sOf + tid * 4);
        *(float4*)(out + (size_t)(tid >> 1) * NPIXC + p0 + (tid & 1) * 4) = v;
    }
}

extern "C" void kernel_launch(void* const* d_in, const int* in_sizes, int n_in,
                              void* d_out, int out_size)
{
    const float* y    = (const float*)d_in[0];
    const float* nz   = (const float*)d_in[1];
    const float* nz2  = (const float*)d_in[2];
    const float* wmap = (const float*)d_in[3];
    const float* w1   = (const float*)d_in[4];
    const float* b1   = (const float*)d_in[5];
    const float* w2   = (const float*)d_in[6];
    const float* b2   = (const float*)d_in[7];
    const int*   nidx = (const int*)d_in[8];
    float* out = (float*)d_out;

    cudaFuncSetAttribute(lr_kernel, cudaFuncAttributeMaxDynamicSharedMemorySize, SMEM_BYTES);
    lr_kernel<<<NPIXC / PXB, THREADS, SMEM_BYTES>>>(y, nz, nz2, wmap, w1, b1, w2, b2, nidx, out);
}